// round 14
// baseline (speedup 1.0000x reference)
#include <cuda_runtime.h>
#include <cuda_bf16.h>
#include <math.h>
#include <stdint.h>

#define BATCH 16384
#define DIN   512
#define HDIM  256

// -------- scratch (static device allocations; no cudaMalloc allowed) --------
__device__ float g_spec[8 * BATCH * HDIM];            // [z][b][h]
__device__ float g_shared[4 * BATCH * HDIM];          // [e][b][h]
__device__ float g_gw[4 * BATCH * 6];                 // FINAL domain gate weights
__device__ float g_gsw[BATCH * 12];                   // FINAL shared gate weights
__device__ float g_wgt[36 * DIN];                     // TRANSPOSED gate weights [e][k]
__device__ __nv_bfloat16 g_whi[12 * DIN * HDIM];      // [z][k][n]
__device__ __nv_bfloat16 g_wlo[12 * DIN * HDIM];

// ============================================================================
// helpers
// ============================================================================
__device__ __forceinline__ uint32_t smem_u32(const void* p) {
    uint32_t a;
    asm("{ .reg .u64 t; cvta.to.shared.u64 t, %1; cvt.u32.u64 %0, t; }" : "=r"(a) : "l"(p));
    return a;
}
__device__ __forceinline__ void cpasync16(uint32_t dst, const void* src) {
    asm volatile("cp.async.cg.shared.global [%0], [%1], 16;" :: "r"(dst), "l"(src) : "memory");
}
#define CP_COMMIT() asm volatile("cp.async.commit_group;" ::: "memory")
#define CP_WAIT1()  asm volatile("cp.async.wait_group 1;" ::: "memory")

__device__ __forceinline__ void ldsm4t(uint32_t& r0, uint32_t& r1, uint32_t& r2, uint32_t& r3, uint32_t addr) {
    asm volatile("ldmatrix.sync.aligned.m8n8.x4.trans.shared.b16 {%0,%1,%2,%3}, [%4];"
                 : "=r"(r0), "=r"(r1), "=r"(r2), "=r"(r3) : "r"(addr));
}
__device__ __forceinline__ void mma16816(float* d, const uint32_t* a, uint32_t b0, uint32_t b1) {
    asm volatile(
        "mma.sync.aligned.m16n8k16.row.col.f32.bf16.bf16.f32 "
        "{%0,%1,%2,%3}, {%4,%5,%6,%7}, {%8,%9}, {%0,%1,%2,%3};"
        : "+f"(d[0]), "+f"(d[1]), "+f"(d[2]), "+f"(d[3])
        : "r"(a[0]), "r"(a[1]), "r"(a[2]), "r"(a[3]), "r"(b0), "r"(b1));
}

// Fast hi/lo bf16 split (packed cvt; bit-identical to scalar __float2bfloat16)
__device__ __forceinline__ void split2(float a0, float a1, uint32_t& hi, uint32_t& lo) {
    uint32_t h;
    asm("cvt.rn.bf16x2.f32 %0, %1, %2;" : "=r"(h) : "f"(a1), "f"(a0));
    const float h0f = __uint_as_float(h << 16);
    const float h1f = __uint_as_float(h & 0xffff0000u);
    const float l0 = a0 - h0f;
    const float l1 = a1 - h1f;
    uint32_t l;
    asm("cvt.rn.bf16x2.f32 %0, %1, %2;" : "=r"(l) : "f"(l1), "f"(l0));
    hi = h; lo = l;
}

// ============================================================================
// Prep kernel: weight split f32->bf16 hi/lo + gate-weight transpose.
// ============================================================================
#define NWS4 (8 * DIN * HDIM / 4)           // 262144 float4
#define NWH4 (4 * DIN * HDIM / 4)           // 131072
#define WSBLK   (NWS4 / 1024)               // 256
#define WHBLK   (NWH4 / 1024)               // 128
#define WBLOCKS (WSBLK + WHBLK)             // 384
#define TBLOCKS 72                          // 18432 gate-weight elements / 256

__global__ __launch_bounds__(256)
void prep_kernel(const float4* __restrict__ Ws, const float4* __restrict__ Wh,
                 const float* __restrict__ Wg, const float* __restrict__ Wgs)
{
    if (blockIdx.x < WBLOCKS) {
        const float4* src;
        size_t dst0;
        if (blockIdx.x < WSBLK) {
            src  = Ws + (size_t)blockIdx.x * 1024;
            dst0 = (size_t)blockIdx.x * 1024;
        } else {
            src  = Wh + (size_t)(blockIdx.x - WSBLK) * 1024;
            dst0 = (size_t)NWS4 + (size_t)(blockIdx.x - WSBLK) * 1024;
        }
        const int t = threadIdx.x;
        float4 v0 = src[t];
        float4 v1 = src[t + 256];
        float4 v2 = src[t + 512];
        float4 v3 = src[t + 768];
        uint2* dh = (uint2*)g_whi;
        uint2* dl = (uint2*)g_wlo;
        uint32_t ha, la, hb, lb;
        split2(v0.x, v0.y, ha, la); split2(v0.z, v0.w, hb, lb);
        dh[dst0 + t]       = make_uint2(ha, hb); dl[dst0 + t]       = make_uint2(la, lb);
        split2(v1.x, v1.y, ha, la); split2(v1.z, v1.w, hb, lb);
        dh[dst0 + t + 256] = make_uint2(ha, hb); dl[dst0 + t + 256] = make_uint2(la, lb);
        split2(v2.x, v2.y, ha, la); split2(v2.z, v2.w, hb, lb);
        dh[dst0 + t + 512] = make_uint2(ha, hb); dl[dst0 + t + 512] = make_uint2(la, lb);
        split2(v3.x, v3.y, ha, la); split2(v3.z, v3.w, hb, lb);
        dh[dst0 + t + 768] = make_uint2(ha, hb); dl[dst0 + t + 768] = make_uint2(la, lb);
        return;
    }

    // gate-weight transpose: read coalesced, scatter to [e][k] rows
    const int idx = (blockIdx.x - WBLOCKS) * 256 + threadIdx.x;
    const int NDOM = 4 * DIN * 6;   // 12288
    if (idx < NDOM) {
        const int n = idx / (DIN * 6);
        const int rem = idx - n * DIN * 6;
        const int k = rem / 6;
        const int e = rem - k * 6;
        g_wgt[(n * 6 + e) * DIN + k] = Wg[idx];
    } else {
        const int j = idx - NDOM;   // < 6144
        const int k = j / 12;
        const int e = j - k * 12;
        g_wgt[(24 + e) * DIN + k] = Wgs[j];
    }
}

// ============================================================================
// Gates device function: one warp computes final gate weights for row b.
// ============================================================================
__device__ __forceinline__ void gates_row(
    const float* __restrict__ x, int b, int lane,
    const float* __restrict__ bg, const float* __restrict__ bgs,
    const int* __restrict__ sim)
{
#pragma unroll
    for (int n = 0; n < 4; ++n) {
        const float* xr = x + ((size_t)n * BATCH + b) * DIN;
        float xv[16];
#pragma unroll
        for (int i = 0; i < 16; ++i) xv[i] = xr[lane + 32 * i];
        float zz[6];
#pragma unroll
        for (int e = 0; e < 6; ++e) {
            const float* wrow = g_wgt + (n * 6 + e) * DIN;
            float acc = 0.f;
#pragma unroll
            for (int i = 0; i < 16; ++i)
                acc = fmaf(xv[i], wrow[lane + 32 * i], acc);
#pragma unroll
            for (int o = 16; o; o >>= 1) acc += __shfl_xor_sync(0xffffffffu, acc, o);
            zz[e] = acc + bg[n * 6 + e];
        }
        float m1 = zz[0];
#pragma unroll
        for (int e = 1; e < 6; ++e) m1 = fmaxf(m1, zz[e]);
        float s1 = 0.f;
#pragma unroll
        for (int e = 0; e < 6; ++e) { zz[e] = __expf(zz[e] - m1); s1 += zz[e]; }
        const float inv1 = 1.f / s1;
#pragma unroll
        for (int e = 0; e < 6; ++e) zz[e] *= inv1;

        const int s0 = sim[n * 2], s1i = sim[n * 2 + 1];
        bool valid[6];
        valid[0] = true; valid[1] = true;
#pragma unroll
        for (int e = 0; e < 4; ++e) valid[2 + e] = (s0 == e) || (s1i == e);
        float m2 = -1e30f;
#pragma unroll
        for (int e = 0; e < 6; ++e) if (valid[e]) m2 = fmaxf(m2, zz[e]);
        float w[6]; float s2 = 0.f;
#pragma unroll
        for (int e = 0; e < 6; ++e) { w[e] = valid[e] ? __expf(zz[e] - m2) : 0.f; s2 += w[e]; }
        const float inv2 = 1.f / s2;
        if (lane == 0) {
#pragma unroll
            for (int e = 0; e < 6; ++e)
                g_gw[((size_t)n * BATCH + b) * 6 + e] = w[e] * inv2;
        }
    }
    {
        const float* xr = x + ((size_t)4 * BATCH + b) * DIN;
        float xv[16];
#pragma unroll
        for (int i = 0; i < 16; ++i) xv[i] = xr[lane + 32 * i];
        float gs[12];
#pragma unroll
        for (int e = 0; e < 12; ++e) {
            const float* wrow = g_wgt + (24 + e) * DIN;
            float acc = 0.f;
#pragma unroll
            for (int i = 0; i < 16; ++i)
                acc = fmaf(xv[i], wrow[lane + 32 * i], acc);
#pragma unroll
            for (int o = 16; o; o >>= 1) acc += __shfl_xor_sync(0xffffffffu, acc, o);
            gs[e] = acc + bgs[e];
        }
        float m = gs[0];
#pragma unroll
        for (int e = 1; e < 12; ++e) m = fmaxf(m, gs[e]);
        float s = 0.f;
#pragma unroll
        for (int e = 0; e < 12; ++e) { gs[e] = __expf(gs[e] - m); s += gs[e]; }
        const float inv = 1.f / s;
        if (lane == 0) {
#pragma unroll
            for (int e = 0; e < 12; ++e)
                g_gsw[(size_t)b * 12 + e] = gs[e] * inv;
        }
    }
}

// ============================================================================
// Fused GEMM + gates kernel. grid = (2, 128, 13).
//   blockIdx.z == 6  -> gates slice (256 CTAs, 64 rows each) — rides the
//                       fma/mufu pipes that the tensor-bound gemm leaves idle,
//                       scheduled mid-sequence so it interleaves with waves.
//   else             -> gemm tile, z' = z<6 ? z : z-1.
// GEMM: A raw f32 -> in-register packed-cvt hi/lo split; B pre-split bf16
// hi/lo via ldmatrix.trans; 3-product accumulation. BK=32, 3-stage cp.async.
// ============================================================================
#define OFF_A   0
#define A_STRIDE 160
#define OFF_BHI 20480
#define OFF_BLO 28672
#define STG     36864
#define GEMM_SMEM (3 * STG)   // 110592

__device__ __forceinline__ void issue_chunk(
    uint32_t sm32, int stage, int c0,
    const float* __restrict__ xz,
    const __nv_bfloat16* __restrict__ whi, const __nv_bfloat16* __restrict__ wlo,
    int m0, int n0, int tid)
{
    const uint32_t sa = sm32 + stage * STG;
#pragma unroll
    for (int i = 0; i < 4; ++i) {
        const int idx = tid + i * 256;
        const int m = idx >> 3, u = idx & 7;
        const float* src = xz + (size_t)(m0 + m) * DIN + c0 + u * 4;
        cpasync16(sa + OFF_A + m * A_STRIDE + u * 16, src);
    }
#pragma unroll
    for (int i = 0; i < 2; ++i) {
        const int idx = tid + i * 256;
        const int k = idx >> 4, u = idx & 15;
        const size_t go = (size_t)(c0 + k) * HDIM + n0 + u * 8;
        const uint32_t phys = (u & 8) | ((u & 7) ^ (k & 7));
        const uint32_t d = sa + OFF_BHI + k * 256 + phys * 16;
        cpasync16(d, whi + go);
        cpasync16(d + (OFF_BLO - OFF_BHI), wlo + go);
    }
}

__global__ void __launch_bounds__(256, 2)
gemm_gates(const float* __restrict__ x,
           const float* __restrict__ bspec, const float* __restrict__ bsh,
           const float* __restrict__ bg,    const float* __restrict__ bgs,
           const int* __restrict__ sim)
{
    extern __shared__ char smem[];
    const int tid  = threadIdx.x;
    const int wid  = tid >> 5;
    const int lane = tid & 31;

    if (blockIdx.z == 6) {
        // ---- gates slice: 256 CTAs x 64 rows; 8 rows per warp ----
        const int base = (blockIdx.y * 2 + blockIdx.x) * 64 + wid * 8;
#pragma unroll
        for (int r = 0; r < 8; ++r)
            gates_row(x, base + r, lane, bg, bgs, sim);
        return;
    }

    const uint32_t sm32 = smem_u32(smem);
    const int wm0  = (wid & 3) * 32;
    const int wn0  = (wid >> 2) * 64;

    const int n0 = blockIdx.x * 128;
    const int m0 = blockIdx.y * 128;
    const int z  = (blockIdx.z < 6) ? blockIdx.z : (blockIdx.z - 1);

    const int zsel = (z < 8) ? (z >> 1) : 4;
    const float* xz = x + (size_t)zsel * BATCH * DIN;
    const __nv_bfloat16* whi = g_whi + (size_t)z * DIN * HDIM;
    const __nv_bfloat16* wlo = g_wlo + (size_t)z * DIN * HDIM;
    const float* bias = (z < 8) ? (bspec + z * HDIM) : (bsh + (z - 8) * HDIM);
    float* outp = (z < 8) ? (g_spec + (size_t)z * BATCH * HDIM)
                          : (g_shared + (size_t)(z - 8) * BATCH * HDIM);

    float acc[2][8][4];
#pragma unroll
    for (int f = 0; f < 2; ++f)
#pragma unroll
        for (int j = 0; j < 8; ++j)
#pragma unroll
            for (int q = 0; q < 4; ++q) acc[f][j][q] = 0.f;

#pragma unroll
    for (int p = 0; p < 2; ++p) {
        issue_chunk(sm32, p, p * 32, xz, whi, wlo, m0, n0, tid);
        CP_COMMIT();
    }

    for (int kt = 0; kt < 16; ++kt) {
        CP_WAIT1();
        __syncthreads();

        if (kt + 2 < 16)
            issue_chunk(sm32, (kt + 2) % 3, (kt + 2) * 32, xz, whi, wlo, m0, n0, tid);
        CP_COMMIT();

        const uint32_t sa = sm32 + (kt % 3) * STG;
        const char* sp = smem + (kt % 3) * STG;
#pragma unroll
        for (int ksb = 0; ksb < 2; ++ksb) {
            const int kb = ksb * 16;
            uint32_t ah[2][4], al[2][4];
#pragma unroll
            for (int f = 0; f < 2; ++f) {
                const char* ap = sp + OFF_A
                    + (wm0 + f * 16 + (lane >> 2)) * A_STRIDE
                    + (kb + ((lane & 3) << 1)) * 4;
                const float2 v0 = *(const float2*)(ap);
                const float2 v1 = *(const float2*)(ap + 8 * A_STRIDE);
                const float2 v2 = *(const float2*)(ap + 32);
                const float2 v3 = *(const float2*)(ap + 8 * A_STRIDE + 32);
                split2(v0.x, v0.y, ah[f][0], al[f][0]);
                split2(v1.x, v1.y, ah[f][1], al[f][1]);
                split2(v2.x, v2.y, ah[f][2], al[f][2]);
                split2(v3.x, v3.y, ah[f][3], al[f][3]);
            }
            const int g = lane >> 3, r = lane & 7;
            const int krow = kb + (g & 1) * 8 + r;
#pragma unroll
            for (int c = 0; c < 4; ++c) {
                const int noff = wn0 + c * 16 + (g >> 1) * 8;
                const uint32_t u = (uint32_t)(noff >> 3);
                const uint32_t phys = (u & 8) | ((u & 7) ^ (uint32_t)(krow & 7));
                const uint32_t baddr = sa + OFF_BHI + krow * 256 + phys * 16;
                uint32_t bh[4], bl[4];
                ldsm4t(bh[0], bh[1], bh[2], bh[3], baddr);
                ldsm4t(bl[0], bl[1], bl[2], bl[3], baddr + (OFF_BLO - OFF_BHI));
#pragma unroll
                for (int f = 0; f < 2; ++f) {
#pragma unroll
                    for (int jj = 0; jj < 2; ++jj) {
                        float* d = acc[f][2 * c + jj];
                        mma16816(d, ah[f], bh[2 * jj], bh[2 * jj + 1]);
                        mma16816(d, ah[f], bl[2 * jj], bl[2 * jj + 1]);
                        mma16816(d, al[f], bh[2 * jj], bh[2 * jj + 1]);
                    }
                }
            }
        }
    }

#pragma unroll
    for (int f = 0; f < 2; ++f) {
#pragma unroll
        for (int j = 0; j < 8; ++j) {
            const int row = m0 + wm0 + f * 16 + (lane >> 2);
            const int col = n0 + wn0 + j * 8 + (lane & 3) * 2;
            const float b0 = __ldg(&bias[col]);
            const float b1 = __ldg(&bias[col + 1]);
            float2 v0, v1;
            v0.x = fmaxf(acc[f][j][0] + b0, 0.f);
            v0.y = fmaxf(acc[f][j][1] + b1, 0.f);
            v1.x = fmaxf(acc[f][j][2] + b0, 0.f);
            v1.y = fmaxf(acc[f][j][3] + b1, 0.f);
            *(float2*)(outp + (size_t)row * HDIM + col)       = v0;
            *(float2*)(outp + (size_t)(row + 8) * HDIM + col) = v1;
        }
    }
}

// ============================================================================
// Combine: 4 rows per block, float4 per thread, no transcendentals.
// ============================================================================
__global__ __launch_bounds__(256)
void combine_kernel(float* __restrict__ out)
{
    __shared__ float w[4][36];
    const int b0  = blockIdx.x * 4;
    const int tid = threadIdx.x;
    if (tid < 144) {
        const int row = tid / 36, e = tid % 36;
        float v;
        if (e < 24) v = g_gw[((size_t)(e / 6) * BATCH + b0 + row) * 6 + (e % 6)];
        else        v = g_gsw[(size_t)(b0 + row) * 12 + (e - 24)];
        w[row][e] = v;
    }
    __syncthreads();

    const int r = tid >> 6;
    const int b = b0 + r;
    const int h = (tid & 63) * 4;

    float4 sp[8];
#pragma unroll
    for (int j = 0; j < 8; ++j)
        sp[j] = *(const float4*)&g_spec[((size_t)j * BATCH + b) * HDIM + h];
    float4 sh[4];
#pragma unroll
    for (int e = 0; e < 4; ++e)
        sh[e] = *(const float4*)&g_shared[((size_t)e * BATCH + b) * HDIM + h];

    {
        float4 o = make_float4(0.f, 0.f, 0.f, 0.f);
#pragma unroll
        for (int j = 0; j < 8; ++j) {
            const float ww = w[r][24 + j];
            o.x = fmaf(ww, sp[j].x, o.x); o.y = fmaf(ww, sp[j].y, o.y);
            o.z = fmaf(ww, sp[j].z, o.z); o.w = fmaf(ww, sp[j].w, o.w);
        }
#pragma unroll
        for (int e = 0; e < 4; ++e) {
            const float ww = w[r][32 + e];
            o.x = fmaf(ww, sh[e].x, o.x); o.y = fmaf(ww, sh[e].y, o.y);
            o.z = fmaf(ww, sh[e].z, o.z); o.w = fmaf(ww, sh[e].w, o.w);
        }
        *(float4*)&out[((size_t)4 * BATCH + b) * HDIM + h] = o;
    }

#pragma unroll
    for (int n = 0; n < 4; ++n) {
        float4 o = make_float4(0.f, 0.f, 0.f, 0.f);
        const float w0 = w[r][n * 6 + 0], w1 = w[r][n * 6 + 1];
        o.x = w0 * sp[2 * n].x + w1 * sp[2 * n + 1].x;
        o.y = w0 * sp[2 * n].y + w1 * sp[2 * n + 1].y;
        o.z = w0 * sp[2 * n].z + w1 * sp[2 * n + 1].z;
        o.w = w0 * sp[2 * n].w + w1 * sp[2 * n + 1].w;
#pragma unroll
        for (int e = 0; e < 4; ++e) {
            const float ww = w[r][n * 6 + 2 + e];
            o.x = fmaf(ww, sh[e].x, o.x); o.y = fmaf(ww, sh[e].y, o.y);
            o.z = fmaf(ww, sh[e].z, o.z); o.w = fmaf(ww, sh[e].w, o.w);
        }
        *(float4*)&out[((size_t)n * BATCH + b) * HDIM + h] = o;
    }
}

// ============================================================================
extern "C" void kernel_launch(void* const* d_in, const int* in_sizes, int n_in,
                              void* d_out, int out_size)
{
    const float* x     = (const float*)d_in[0];
    const int*   sim   = (const int*)d_in[1];
    const float* Wspec = (const float*)d_in[2];
    const float* bspec = (const float*)d_in[3];
    const float* Wsh   = (const float*)d_in[4];
    const float* bsh   = (const float*)d_in[5];
    const float* Wg    = (const float*)d_in[6];
    const float* bg    = (const float*)d_in[7];
    const float* Wgs   = (const float*)d_in[8];
    const float* bgs   = (const float*)d_in[9];
    float* out = (float*)d_out;

    prep_kernel<<<WBLOCKS + TBLOCKS, 256>>>(
        (const float4*)Wspec, (const float4*)Wsh, Wg, Wgs);

    cudaFuncSetAttribute(gemm_gates, cudaFuncAttributeMaxDynamicSharedMemorySize, GEMM_SMEM);
    dim3 gemm_grid(2, 128, 13);
    gemm_gates<<<gemm_grid, 256, GEMM_SMEM>>>(x, bspec, bsh, bg, bgs, sim);

    combine_kernel<<<BATCH / 4, 256>>>(out);
}

// round 15
// speedup vs baseline: 1.3034x; 1.3034x over previous
#include <cuda_runtime.h>
#include <cuda_bf16.h>
#include <math.h>
#include <stdint.h>

#define BATCH 16384
#define DIN   512
#define HDIM  256

// -------- scratch (static device allocations; no cudaMalloc allowed) --------
__device__ float g_spec[8 * BATCH * HDIM];            // [z][b][h]
__device__ float g_shared[4 * BATCH * HDIM];          // [e][b][h]
__device__ float g_gw[4 * BATCH * 6];                 // FINAL domain gate weights
__device__ float g_gsw[BATCH * 12];                   // FINAL shared gate weights
__device__ float g_wgt[36 * DIN];                     // TRANSPOSED gate weights [e][k]
__device__ __nv_bfloat16 g_whi[12 * DIN * HDIM];      // [z][k][n]
__device__ __nv_bfloat16 g_wlo[12 * DIN * HDIM];

// ============================================================================
// helpers
// ============================================================================
__device__ __forceinline__ uint32_t smem_u32(const void* p) {
    uint32_t a;
    asm("{ .reg .u64 t; cvta.to.shared.u64 t, %1; cvt.u32.u64 %0, t; }" : "=r"(a) : "l"(p));
    return a;
}
__device__ __forceinline__ void cpasync16(uint32_t dst, const void* src) {
    asm volatile("cp.async.cg.shared.global [%0], [%1], 16;" :: "r"(dst), "l"(src) : "memory");
}
#define CP_COMMIT() asm volatile("cp.async.commit_group;" ::: "memory")
#define CP_WAIT1()  asm volatile("cp.async.wait_group 1;" ::: "memory")

__device__ __forceinline__ void ldsm4t(uint32_t& r0, uint32_t& r1, uint32_t& r2, uint32_t& r3, uint32_t addr) {
    asm volatile("ldmatrix.sync.aligned.m8n8.x4.trans.shared.b16 {%0,%1,%2,%3}, [%4];"
                 : "=r"(r0), "=r"(r1), "=r"(r2), "=r"(r3) : "r"(addr));
}
__device__ __forceinline__ void mma16816(float* d, const uint32_t* a, uint32_t b0, uint32_t b1) {
    asm volatile(
        "mma.sync.aligned.m16n8k16.row.col.f32.bf16.bf16.f32 "
        "{%0,%1,%2,%3}, {%4,%5,%6,%7}, {%8,%9}, {%0,%1,%2,%3};"
        : "+f"(d[0]), "+f"(d[1]), "+f"(d[2]), "+f"(d[3])
        : "r"(a[0]), "r"(a[1]), "r"(a[2]), "r"(a[3]), "r"(b0), "r"(b1));
}

// Fast hi/lo bf16 split (packed cvt; bit-identical to scalar __float2bfloat16)
__device__ __forceinline__ void split2(float a0, float a1, uint32_t& hi, uint32_t& lo) {
    uint32_t h;
    asm("cvt.rn.bf16x2.f32 %0, %1, %2;" : "=r"(h) : "f"(a1), "f"(a0));
    const float h0f = __uint_as_float(h << 16);
    const float h1f = __uint_as_float(h & 0xffff0000u);
    const float l0 = a0 - h0f;
    const float l1 = a1 - h1f;
    uint32_t l;
    asm("cvt.rn.bf16x2.f32 %0, %1, %2;" : "=r"(l) : "f"(l1), "f"(l0));
    hi = h; lo = l;
}

// ============================================================================
// Prep kernel: weight split f32->bf16 hi/lo + gate-weight transpose.
// ============================================================================
#define NWS4 (8 * DIN * HDIM / 4)           // 262144 float4
#define NWH4 (4 * DIN * HDIM / 4)           // 131072
#define WSBLK   (NWS4 / 1024)               // 256
#define WHBLK   (NWH4 / 1024)               // 128
#define WBLOCKS (WSBLK + WHBLK)             // 384
#define TBLOCKS 72                          // 18432 gate-weight elements / 256

__global__ __launch_bounds__(256)
void prep_kernel(const float4* __restrict__ Ws, const float4* __restrict__ Wh,
                 const float* __restrict__ Wg, const float* __restrict__ Wgs)
{
    if (blockIdx.x < WBLOCKS) {
        const float4* src;
        size_t dst0;
        if (blockIdx.x < WSBLK) {
            src  = Ws + (size_t)blockIdx.x * 1024;
            dst0 = (size_t)blockIdx.x * 1024;
        } else {
            src  = Wh + (size_t)(blockIdx.x - WSBLK) * 1024;
            dst0 = (size_t)NWS4 + (size_t)(blockIdx.x - WSBLK) * 1024;
        }
        const int t = threadIdx.x;
        float4 v0 = src[t];
        float4 v1 = src[t + 256];
        float4 v2 = src[t + 512];
        float4 v3 = src[t + 768];
        uint2* dh = (uint2*)g_whi;
        uint2* dl = (uint2*)g_wlo;
        uint32_t ha, la, hb, lb;
        split2(v0.x, v0.y, ha, la); split2(v0.z, v0.w, hb, lb);
        dh[dst0 + t]       = make_uint2(ha, hb); dl[dst0 + t]       = make_uint2(la, lb);
        split2(v1.x, v1.y, ha, la); split2(v1.z, v1.w, hb, lb);
        dh[dst0 + t + 256] = make_uint2(ha, hb); dl[dst0 + t + 256] = make_uint2(la, lb);
        split2(v2.x, v2.y, ha, la); split2(v2.z, v2.w, hb, lb);
        dh[dst0 + t + 512] = make_uint2(ha, hb); dl[dst0 + t + 512] = make_uint2(la, lb);
        split2(v3.x, v3.y, ha, la); split2(v3.z, v3.w, hb, lb);
        dh[dst0 + t + 768] = make_uint2(ha, hb); dl[dst0 + t + 768] = make_uint2(la, lb);
        return;
    }

    // gate-weight transpose: read coalesced, scatter to [e][k] rows
    const int idx = (blockIdx.x - WBLOCKS) * 256 + threadIdx.x;
    const int NDOM = 4 * DIN * 6;   // 12288
    if (idx < NDOM) {
        const int n = idx / (DIN * 6);
        const int rem = idx - n * DIN * 6;
        const int k = rem / 6;
        const int e = rem - k * 6;
        g_wgt[(n * 6 + e) * DIN + k] = Wg[idx];
    } else {
        const int j = idx - NDOM;   // < 6144
        const int k = j / 12;
        const int e = j - k * 12;
        g_wgt[(24 + e) * DIN + k] = Wgs[j];
    }
}

// ============================================================================
// Gates: one warp per TWO batch rows (amortizes the g_wgt weight stream:
// each weight load feeds 2 FMAs -> L1 weight traffic halves vs R13).
// Transposed weights from g_wgt (coalesced, L1/L2-hot).
// ============================================================================
__global__ __launch_bounds__(256)
void gates_kernel(const float* __restrict__ x,
                  const float* __restrict__ bg, const float* __restrict__ bgs,
                  const int* __restrict__ sim)
{
    const int wid  = threadIdx.x >> 5;
    const int lane = threadIdx.x & 31;
    const int b0   = blockIdx.x * 16 + wid * 2;   // two rows per warp

#pragma unroll
    for (int n = 0; n < 4; ++n) {
        const float* xr0 = x + ((size_t)n * BATCH + b0) * DIN;
        float xa[16], xb[16];
#pragma unroll
        for (int i = 0; i < 16; ++i) {
            xa[i] = xr0[lane + 32 * i];
            xb[i] = xr0[DIN + lane + 32 * i];
        }
        float za[6], zb[6];
#pragma unroll
        for (int e = 0; e < 6; ++e) {
            const float* wrow = g_wgt + (n * 6 + e) * DIN;
            float a0 = 0.f, a1 = 0.f;
#pragma unroll
            for (int i = 0; i < 16; ++i) {
                const float wv = wrow[lane + 32 * i];
                a0 = fmaf(xa[i], wv, a0);
                a1 = fmaf(xb[i], wv, a1);
            }
#pragma unroll
            for (int o = 16; o; o >>= 1) {
                a0 += __shfl_xor_sync(0xffffffffu, a0, o);
                a1 += __shfl_xor_sync(0xffffffffu, a1, o);
            }
            const float bias = bg[n * 6 + e];
            za[e] = a0 + bias;
            zb[e] = a1 + bias;
        }

        const int s0 = sim[n * 2], s1i = sim[n * 2 + 1];
        bool valid[6];
        valid[0] = true; valid[1] = true;
#pragma unroll
        for (int e = 0; e < 4; ++e) valid[2 + e] = (s0 == e) || (s1i == e);

#pragma unroll
        for (int r = 0; r < 2; ++r) {
            float* zz = (r == 0) ? za : zb;
            float m1 = zz[0];
#pragma unroll
            for (int e = 1; e < 6; ++e) m1 = fmaxf(m1, zz[e]);
            float s1 = 0.f;
#pragma unroll
            for (int e = 0; e < 6; ++e) { zz[e] = __expf(zz[e] - m1); s1 += zz[e]; }
            const float inv1 = 1.f / s1;
#pragma unroll
            for (int e = 0; e < 6; ++e) zz[e] *= inv1;

            float m2 = -1e30f;
#pragma unroll
            for (int e = 0; e < 6; ++e) if (valid[e]) m2 = fmaxf(m2, zz[e]);
            float w[6]; float s2 = 0.f;
#pragma unroll
            for (int e = 0; e < 6; ++e) { w[e] = valid[e] ? __expf(zz[e] - m2) : 0.f; s2 += w[e]; }
            const float inv2 = 1.f / s2;
            if (lane == 0) {
#pragma unroll
                for (int e = 0; e < 6; ++e)
                    g_gw[((size_t)n * BATCH + b0 + r) * 6 + e] = w[e] * inv2;
            }
        }
    }
    {
        const float* xr0 = x + ((size_t)4 * BATCH + b0) * DIN;
        float xa[16], xb[16];
#pragma unroll
        for (int i = 0; i < 16; ++i) {
            xa[i] = xr0[lane + 32 * i];
            xb[i] = xr0[DIN + lane + 32 * i];
        }
        float ga[12], gb[12];
#pragma unroll
        for (int e = 0; e < 12; ++e) {
            const float* wrow = g_wgt + (24 + e) * DIN;
            float a0 = 0.f, a1 = 0.f;
#pragma unroll
            for (int i = 0; i < 16; ++i) {
                const float wv = wrow[lane + 32 * i];
                a0 = fmaf(xa[i], wv, a0);
                a1 = fmaf(xb[i], wv, a1);
            }
#pragma unroll
            for (int o = 16; o; o >>= 1) {
                a0 += __shfl_xor_sync(0xffffffffu, a0, o);
                a1 += __shfl_xor_sync(0xffffffffu, a1, o);
            }
            const float bias = bgs[e];
            ga[e] = a0 + bias;
            gb[e] = a1 + bias;
        }
#pragma unroll
        for (int r = 0; r < 2; ++r) {
            float* gs = (r == 0) ? ga : gb;
            float m = gs[0];
#pragma unroll
            for (int e = 1; e < 12; ++e) m = fmaxf(m, gs[e]);
            float s = 0.f;
#pragma unroll
            for (int e = 0; e < 12; ++e) { gs[e] = __expf(gs[e] - m); s += gs[e]; }
            const float inv = 1.f / s;
            if (lane == 0) {
#pragma unroll
                for (int e = 0; e < 12; ++e)
                    g_gsw[(size_t)(b0 + r) * 12 + e] = gs[e] * inv;
            }
        }
    }
}

// ============================================================================
// Tensor-core GEMM (R13-proven, untouched): A raw f32 -> in-register
// packed-cvt hi/lo split; B pre-split bf16 hi/lo via ldmatrix.trans.
// 3-product accumulation. CTA tile 128x128, BK=32, 3-stage cp.async, 2 CTA/SM.
// ============================================================================
#define OFF_A   0
#define A_STRIDE 160
#define OFF_BHI 20480
#define OFF_BLO 28672
#define STG     36864
#define GEMM_SMEM (3 * STG)   // 110592

__device__ __forceinline__ void issue_chunk(
    uint32_t sm32, int stage, int c0,
    const float* __restrict__ xz,
    const __nv_bfloat16* __restrict__ whi, const __nv_bfloat16* __restrict__ wlo,
    int m0, int n0, int tid)
{
    const uint32_t sa = sm32 + stage * STG;
#pragma unroll
    for (int i = 0; i < 4; ++i) {
        const int idx = tid + i * 256;
        const int m = idx >> 3, u = idx & 7;
        const float* src = xz + (size_t)(m0 + m) * DIN + c0 + u * 4;
        cpasync16(sa + OFF_A + m * A_STRIDE + u * 16, src);
    }
#pragma unroll
    for (int i = 0; i < 2; ++i) {
        const int idx = tid + i * 256;
        const int k = idx >> 4, u = idx & 15;
        const size_t go = (size_t)(c0 + k) * HDIM + n0 + u * 8;
        const uint32_t phys = (u & 8) | ((u & 7) ^ (k & 7));
        const uint32_t d = sa + OFF_BHI + k * 256 + phys * 16;
        cpasync16(d, whi + go);
        cpasync16(d + (OFF_BLO - OFF_BHI), wlo + go);
    }
}

__global__ void __launch_bounds__(256, 2)
gemm_tc(const float* __restrict__ x,
        const float* __restrict__ bspec, const float* __restrict__ bsh)
{
    extern __shared__ char smem[];
    const uint32_t sm32 = smem_u32(smem);
    const int tid  = threadIdx.x;
    const int wid  = tid >> 5;
    const int lane = tid & 31;
    const int wm0  = (wid & 3) * 32;
    const int wn0  = (wid >> 2) * 64;

    const int n0 = blockIdx.x * 128;
    const int m0 = blockIdx.y * 128;
    const int z  = blockIdx.z;

    const int zsel = (z < 8) ? (z >> 1) : 4;
    const float* xz = x + (size_t)zsel * BATCH * DIN;
    const __nv_bfloat16* whi = g_whi + (size_t)z * DIN * HDIM;
    const __nv_bfloat16* wlo = g_wlo + (size_t)z * DIN * HDIM;
    const float* bias = (z < 8) ? (bspec + z * HDIM) : (bsh + (z - 8) * HDIM);
    float* outp = (z < 8) ? (g_spec + (size_t)z * BATCH * HDIM)
                          : (g_shared + (size_t)(z - 8) * BATCH * HDIM);

    float acc[2][8][4];
#pragma unroll
    for (int f = 0; f < 2; ++f)
#pragma unroll
        for (int j = 0; j < 8; ++j)
#pragma unroll
            for (int q = 0; q < 4; ++q) acc[f][j][q] = 0.f;

#pragma unroll
    for (int p = 0; p < 2; ++p) {
        issue_chunk(sm32, p, p * 32, xz, whi, wlo, m0, n0, tid);
        CP_COMMIT();
    }

    for (int kt = 0; kt < 16; ++kt) {
        CP_WAIT1();
        __syncthreads();

        if (kt + 2 < 16)
            issue_chunk(sm32, (kt + 2) % 3, (kt + 2) * 32, xz, whi, wlo, m0, n0, tid);
        CP_COMMIT();

        const uint32_t sa = sm32 + (kt % 3) * STG;
        const char* sp = smem + (kt % 3) * STG;
#pragma unroll
        for (int ksb = 0; ksb < 2; ++ksb) {
            const int kb = ksb * 16;
            uint32_t ah[2][4], al[2][4];
#pragma unroll
            for (int f = 0; f < 2; ++f) {
                const char* ap = sp + OFF_A
                    + (wm0 + f * 16 + (lane >> 2)) * A_STRIDE
                    + (kb + ((lane & 3) << 1)) * 4;
                const float2 v0 = *(const float2*)(ap);
                const float2 v1 = *(const float2*)(ap + 8 * A_STRIDE);
                const float2 v2 = *(const float2*)(ap + 32);
                const float2 v3 = *(const float2*)(ap + 8 * A_STRIDE + 32);
                split2(v0.x, v0.y, ah[f][0], al[f][0]);
                split2(v1.x, v1.y, ah[f][1], al[f][1]);
                split2(v2.x, v2.y, ah[f][2], al[f][2]);
                split2(v3.x, v3.y, ah[f][3], al[f][3]);
            }
            const int g = lane >> 3, r = lane & 7;
            const int krow = kb + (g & 1) * 8 + r;
#pragma unroll
            for (int c = 0; c < 4; ++c) {
                const int noff = wn0 + c * 16 + (g >> 1) * 8;
                const uint32_t u = (uint32_t)(noff >> 3);
                const uint32_t phys = (u & 8) | ((u & 7) ^ (uint32_t)(krow & 7));
                const uint32_t baddr = sa + OFF_BHI + krow * 256 + phys * 16;
                uint32_t bh[4], bl[4];
                ldsm4t(bh[0], bh[1], bh[2], bh[3], baddr);
                ldsm4t(bl[0], bl[1], bl[2], bl[3], baddr + (OFF_BLO - OFF_BHI));
#pragma unroll
                for (int f = 0; f < 2; ++f) {
#pragma unroll
                    for (int jj = 0; jj < 2; ++jj) {
                        float* d = acc[f][2 * c + jj];
                        mma16816(d, ah[f], bh[2 * jj], bh[2 * jj + 1]);
                        mma16816(d, ah[f], bl[2 * jj], bl[2 * jj + 1]);
                        mma16816(d, al[f], bh[2 * jj], bh[2 * jj + 1]);
                    }
                }
            }
        }
    }

#pragma unroll
    for (int f = 0; f < 2; ++f) {
#pragma unroll
        for (int j = 0; j < 8; ++j) {
            const int row = m0 + wm0 + f * 16 + (lane >> 2);
            const int col = n0 + wn0 + j * 8 + (lane & 3) * 2;
            const float b0 = __ldg(&bias[col]);
            const float b1 = __ldg(&bias[col + 1]);
            float2 v0, v1;
            v0.x = fmaxf(acc[f][j][0] + b0, 0.f);
            v0.y = fmaxf(acc[f][j][1] + b1, 0.f);
            v1.x = fmaxf(acc[f][j][2] + b0, 0.f);
            v1.y = fmaxf(acc[f][j][3] + b1, 0.f);
            *(float2*)(outp + (size_t)row * HDIM + col)       = v0;
            *(float2*)(outp + (size_t)(row + 8) * HDIM + col) = v1;
        }
    }
}

// ============================================================================
// Combine: 4 rows per block, float4 per thread, no transcendentals.
// ============================================================================
__global__ __launch_bounds__(256)
void combine_kernel(float* __restrict__ out)
{
    __shared__ float w[4][36];
    const int b0  = blockIdx.x * 4;
    const int tid = threadIdx.x;
    if (tid < 144) {
        const int row = tid / 36, e = tid % 36;
        float v;
        if (e < 24) v = g_gw[((size_t)(e / 6) * BATCH + b0 + row) * 6 + (e % 6)];
        else        v = g_gsw[(size_t)(b0 + row) * 12 + (e - 24)];
        w[row][e] = v;
    }
    __syncthreads();

    const int r = tid >> 6;
    const int b = b0 + r;
    const int h = (tid & 63) * 4;

    float4 sp[8];
#pragma unroll
    for (int j = 0; j < 8; ++j)
        sp[j] = *(const float4*)&g_spec[((size_t)j * BATCH + b) * HDIM + h];
    float4 sh[4];
#pragma unroll
    for (int e = 0; e < 4; ++e)
        sh[e] = *(const float4*)&g_shared[((size_t)e * BATCH + b) * HDIM + h];

    {
        float4 o = make_float4(0.f, 0.f, 0.f, 0.f);
#pragma unroll
        for (int j = 0; j < 8; ++j) {
            const float ww = w[r][24 + j];
            o.x = fmaf(ww, sp[j].x, o.x); o.y = fmaf(ww, sp[j].y, o.y);
            o.z = fmaf(ww, sp[j].z, o.z); o.w = fmaf(ww, sp[j].w, o.w);
        }
#pragma unroll
        for (int e = 0; e < 4; ++e) {
            const float ww = w[r][32 + e];
            o.x = fmaf(ww, sh[e].x, o.x); o.y = fmaf(ww, sh[e].y, o.y);
            o.z = fmaf(ww, sh[e].z, o.z); o.w = fmaf(ww, sh[e].w, o.w);
        }
        *(float4*)&out[((size_t)4 * BATCH + b) * HDIM + h] = o;
    }

#pragma unroll
    for (int n = 0; n < 4; ++n) {
        float4 o = make_float4(0.f, 0.f, 0.f, 0.f);
        const float w0 = w[r][n * 6 + 0], w1 = w[r][n * 6 + 1];
        o.x = w0 * sp[2 * n].x + w1 * sp[2 * n + 1].x;
        o.y = w0 * sp[2 * n].y + w1 * sp[2 * n + 1].y;
        o.z = w0 * sp[2 * n].z + w1 * sp[2 * n + 1].z;
        o.w = w0 * sp[2 * n].w + w1 * sp[2 * n + 1].w;
#pragma unroll
        for (int e = 0; e < 4; ++e) {
            const float ww = w[r][n * 6 + 2 + e];
            o.x = fmaf(ww, sh[e].x, o.x); o.y = fmaf(ww, sh[e].y, o.y);
            o.z = fmaf(ww, sh[e].z, o.z); o.w = fmaf(ww, sh[e].w, o.w);
        }
        *(float4*)&out[((size_t)n * BATCH + b) * HDIM + h] = o;
    }
}

// ============================================================================
extern "C" void kernel_launch(void* const* d_in, const int* in_sizes, int n_in,
                              void* d_out, int out_size)
{
    const float* x     = (const float*)d_in[0];
    const int*   sim   = (const int*)d_in[1];
    const float* Wspec = (const float*)d_in[2];
    const float* bspec = (const float*)d_in[3];
    const float* Wsh   = (const float*)d_in[4];
    const float* bsh   = (const float*)d_in[5];
    const float* Wg    = (const float*)d_in[6];
    const float* bg    = (const float*)d_in[7];
    const float* Wgs   = (const float*)d_in[8];
    const float* bgs   = (const float*)d_in[9];
    float* out = (float*)d_out;

    prep_kernel<<<WBLOCKS + TBLOCKS, 256>>>(
        (const float4*)Wspec, (const float4*)Wsh, Wg, Wgs);

    gates_kernel<<<BATCH / 16, 256>>>(x, bg, bgs, sim);

    cudaFuncSetAttribute(gemm_tc, cudaFuncAttributeMaxDynamicSharedMemorySize, GEMM_SMEM);
    dim3 gemm_grid(2, 128, 12);
    gemm_tc<<<gemm_grid, 256, GEMM_SMEM>>>(x, bspec, bsh);

    combine_kernel<<<BATCH / 4, 256>>>(out);
}

// round 16
// speedup vs baseline: 1.3872x; 1.0643x over previous
#include <cuda_runtime.h>
#include <cuda_bf16.h>
#include <cuda_fp16.h>
#include <math.h>
#include <stdint.h>

#define BATCH 16384
#define DIN   512
#define HDIM  256

// -------- scratch (static device allocations; no cudaMalloc allowed) --------
__device__ __half g_spec[8 * BATCH * HDIM];           // [z][b][h] fp16 scratch
__device__ __half g_shared[4 * BATCH * HDIM];         // [e][b][h] fp16 scratch
__device__ float g_gw[4 * BATCH * 6];                 // FINAL domain gate weights
__device__ float g_gsw[BATCH * 12];                   // FINAL shared gate weights
__device__ float g_wgt[36 * DIN];                     // TRANSPOSED gate weights [e][k]
__device__ __nv_bfloat16 g_whi[12 * DIN * HDIM];      // [z][k][n]
__device__ __nv_bfloat16 g_wlo[12 * DIN * HDIM];

// ============================================================================
// helpers
// ============================================================================
__device__ __forceinline__ uint32_t smem_u32(const void* p) {
    uint32_t a;
    asm("{ .reg .u64 t; cvta.to.shared.u64 t, %1; cvt.u32.u64 %0, t; }" : "=r"(a) : "l"(p));
    return a;
}
__device__ __forceinline__ void cpasync16(uint32_t dst, const void* src) {
    asm volatile("cp.async.cg.shared.global [%0], [%1], 16;" :: "r"(dst), "l"(src) : "memory");
}
#define CP_COMMIT() asm volatile("cp.async.commit_group;" ::: "memory")
#define CP_WAIT1()  asm volatile("cp.async.wait_group 1;" ::: "memory")

__device__ __forceinline__ void ldsm4t(uint32_t& r0, uint32_t& r1, uint32_t& r2, uint32_t& r3, uint32_t addr) {
    asm volatile("ldmatrix.sync.aligned.m8n8.x4.trans.shared.b16 {%0,%1,%2,%3}, [%4];"
                 : "=r"(r0), "=r"(r1), "=r"(r2), "=r"(r3) : "r"(addr));
}
__device__ __forceinline__ void mma16816(float* d, const uint32_t* a, uint32_t b0, uint32_t b1) {
    asm volatile(
        "mma.sync.aligned.m16n8k16.row.col.f32.bf16.bf16.f32 "
        "{%0,%1,%2,%3}, {%4,%5,%6,%7}, {%8,%9}, {%0,%1,%2,%3};"
        : "+f"(d[0]), "+f"(d[1]), "+f"(d[2]), "+f"(d[3])
        : "r"(a[0]), "r"(a[1]), "r"(a[2]), "r"(a[3]), "r"(b0), "r"(b1));
}

// Fast hi/lo bf16 split (packed cvt; bit-identical to scalar __float2bfloat16)
__device__ __forceinline__ void split2(float a0, float a1, uint32_t& hi, uint32_t& lo) {
    uint32_t h;
    asm("cvt.rn.bf16x2.f32 %0, %1, %2;" : "=r"(h) : "f"(a1), "f"(a0));
    const float h0f = __uint_as_float(h << 16);
    const float h1f = __uint_as_float(h & 0xffff0000u);
    const float l0 = a0 - h0f;
    const float l1 = a1 - h1f;
    uint32_t l;
    asm("cvt.rn.bf16x2.f32 %0, %1, %2;" : "=r"(l) : "f"(l1), "f"(l0));
    hi = h; lo = l;
}

// load 4 consecutive fp16 -> float4
__device__ __forceinline__ float4 ld_half4(const __half* p) {
    const uint2 u = *(const uint2*)p;
    const __half2 a = *(const __half2*)&u.x;
    const __half2 b = *(const __half2*)&u.y;
    const float2 fa = __half22float2(a);
    const float2 fb = __half22float2(b);
    return make_float4(fa.x, fa.y, fb.x, fb.y);
}

// ============================================================================
// Prep kernel: weight split f32->bf16 hi/lo + gate-weight transpose.
// ============================================================================
#define NWS4 (8 * DIN * HDIM / 4)           // 262144 float4
#define NWH4 (4 * DIN * HDIM / 4)           // 131072
#define WSBLK   (NWS4 / 1024)               // 256
#define WHBLK   (NWH4 / 1024)               // 128
#define WBLOCKS (WSBLK + WHBLK)             // 384
#define TBLOCKS 72                          // 18432 gate-weight elements / 256

__global__ __launch_bounds__(256)
void prep_kernel(const float4* __restrict__ Ws, const float4* __restrict__ Wh,
                 const float* __restrict__ Wg, const float* __restrict__ Wgs)
{
    if (blockIdx.x < WBLOCKS) {
        const float4* src;
        size_t dst0;
        if (blockIdx.x < WSBLK) {
            src  = Ws + (size_t)blockIdx.x * 1024;
            dst0 = (size_t)blockIdx.x * 1024;
        } else {
            src  = Wh + (size_t)(blockIdx.x - WSBLK) * 1024;
            dst0 = (size_t)NWS4 + (size_t)(blockIdx.x - WSBLK) * 1024;
        }
        const int t = threadIdx.x;
        float4 v0 = src[t];
        float4 v1 = src[t + 256];
        float4 v2 = src[t + 512];
        float4 v3 = src[t + 768];
        uint2* dh = (uint2*)g_whi;
        uint2* dl = (uint2*)g_wlo;
        uint32_t ha, la, hb, lb;
        split2(v0.x, v0.y, ha, la); split2(v0.z, v0.w, hb, lb);
        dh[dst0 + t]       = make_uint2(ha, hb); dl[dst0 + t]       = make_uint2(la, lb);
        split2(v1.x, v1.y, ha, la); split2(v1.z, v1.w, hb, lb);
        dh[dst0 + t + 256] = make_uint2(ha, hb); dl[dst0 + t + 256] = make_uint2(la, lb);
        split2(v2.x, v2.y, ha, la); split2(v2.z, v2.w, hb, lb);
        dh[dst0 + t + 512] = make_uint2(ha, hb); dl[dst0 + t + 512] = make_uint2(la, lb);
        split2(v3.x, v3.y, ha, la); split2(v3.z, v3.w, hb, lb);
        dh[dst0 + t + 768] = make_uint2(ha, hb); dl[dst0 + t + 768] = make_uint2(la, lb);
        return;
    }

    // gate-weight transpose: read coalesced, scatter to [e][k] rows
    const int idx = (blockIdx.x - WBLOCKS) * 256 + threadIdx.x;
    const int NDOM = 4 * DIN * 6;   // 12288
    if (idx < NDOM) {
        const int n = idx / (DIN * 6);
        const int rem = idx - n * DIN * 6;
        const int k = rem / 6;
        const int e = rem - k * 6;
        g_wgt[(n * 6 + e) * DIN + k] = Wg[idx];
    } else {
        const int j = idx - NDOM;   // < 6144
        const int k = j / 12;
        const int e = j - k * 12;
        g_wgt[(24 + e) * DIN + k] = Wgs[j];
    }
}

// ============================================================================
// Gates (R13-proven): warp per row, transposed weights from g_wgt.
// ============================================================================
__global__ __launch_bounds__(256)
void gates_kernel(const float* __restrict__ x,
                  const float* __restrict__ bg, const float* __restrict__ bgs,
                  const int* __restrict__ sim)
{
    const int b    = blockIdx.x * 8 + (threadIdx.x >> 5);
    const int lane = threadIdx.x & 31;

#pragma unroll
    for (int n = 0; n < 4; ++n) {
        const float* xr = x + ((size_t)n * BATCH + b) * DIN;
        float xv[16];
#pragma unroll
        for (int i = 0; i < 16; ++i) xv[i] = xr[lane + 32 * i];
        float zz[6];
#pragma unroll
        for (int e = 0; e < 6; ++e) {
            const float* wrow = g_wgt + (n * 6 + e) * DIN;
            float acc = 0.f;
#pragma unroll
            for (int i = 0; i < 16; ++i)
                acc = fmaf(xv[i], wrow[lane + 32 * i], acc);
#pragma unroll
            for (int o = 16; o; o >>= 1) acc += __shfl_xor_sync(0xffffffffu, acc, o);
            zz[e] = acc + bg[n * 6 + e];
        }
        float m1 = zz[0];
#pragma unroll
        for (int e = 1; e < 6; ++e) m1 = fmaxf(m1, zz[e]);
        float s1 = 0.f;
#pragma unroll
        for (int e = 0; e < 6; ++e) { zz[e] = __expf(zz[e] - m1); s1 += zz[e]; }
        const float inv1 = 1.f / s1;
#pragma unroll
        for (int e = 0; e < 6; ++e) zz[e] *= inv1;

        const int s0 = sim[n * 2], s1i = sim[n * 2 + 1];
        bool valid[6];
        valid[0] = true; valid[1] = true;
#pragma unroll
        for (int e = 0; e < 4; ++e) valid[2 + e] = (s0 == e) || (s1i == e);
        float m2 = -1e30f;
#pragma unroll
        for (int e = 0; e < 6; ++e) if (valid[e]) m2 = fmaxf(m2, zz[e]);
        float w[6]; float s2 = 0.f;
#pragma unroll
        for (int e = 0; e < 6; ++e) { w[e] = valid[e] ? __expf(zz[e] - m2) : 0.f; s2 += w[e]; }
        const float inv2 = 1.f / s2;
        if (lane == 0) {
#pragma unroll
            for (int e = 0; e < 6; ++e)
                g_gw[((size_t)n * BATCH + b) * 6 + e] = w[e] * inv2;
        }
    }
    {
        const float* xr = x + ((size_t)4 * BATCH + b) * DIN;
        float xv[16];
#pragma unroll
        for (int i = 0; i < 16; ++i) xv[i] = xr[lane + 32 * i];
        float gs[12];
#pragma unroll
        for (int e = 0; e < 12; ++e) {
            const float* wrow = g_wgt + (24 + e) * DIN;
            float acc = 0.f;
#pragma unroll
            for (int i = 0; i < 16; ++i)
                acc = fmaf(xv[i], wrow[lane + 32 * i], acc);
#pragma unroll
            for (int o = 16; o; o >>= 1) acc += __shfl_xor_sync(0xffffffffu, acc, o);
            gs[e] = acc + bgs[e];
        }
        float m = gs[0];
#pragma unroll
        for (int e = 1; e < 12; ++e) m = fmaxf(m, gs[e]);
        float s = 0.f;
#pragma unroll
        for (int e = 0; e < 12; ++e) { gs[e] = __expf(gs[e] - m); s += gs[e]; }
        const float inv = 1.f / s;
        if (lane == 0) {
#pragma unroll
            for (int e = 0; e < 12; ++e)
                g_gsw[(size_t)b * 12 + e] = gs[e] * inv;
        }
    }
}

// ============================================================================
// Tensor-core GEMM (R13-proven loop, fp16 epilogue): A raw f32 -> in-register
// packed-cvt hi/lo split; B pre-split bf16 hi/lo via ldmatrix.trans.
// 3-product accumulation. CTA tile 128x128, BK=32, 3-stage cp.async, 2 CTA/SM.
// ============================================================================
#define OFF_A   0
#define A_STRIDE 160
#define OFF_BHI 20480
#define OFF_BLO 28672
#define STG     36864
#define GEMM_SMEM (3 * STG)   // 110592

__device__ __forceinline__ void issue_chunk(
    uint32_t sm32, int stage, int c0,
    const float* __restrict__ xz,
    const __nv_bfloat16* __restrict__ whi, const __nv_bfloat16* __restrict__ wlo,
    int m0, int n0, int tid)
{
    const uint32_t sa = sm32 + stage * STG;
#pragma unroll
    for (int i = 0; i < 4; ++i) {
        const int idx = tid + i * 256;
        const int m = idx >> 3, u = idx & 7;
        const float* src = xz + (size_t)(m0 + m) * DIN + c0 + u * 4;
        cpasync16(sa + OFF_A + m * A_STRIDE + u * 16, src);
    }
#pragma unroll
    for (int i = 0; i < 2; ++i) {
        const int idx = tid + i * 256;
        const int k = idx >> 4, u = idx & 15;
        const size_t go = (size_t)(c0 + k) * HDIM + n0 + u * 8;
        const uint32_t phys = (u & 8) | ((u & 7) ^ (k & 7));
        const uint32_t d = sa + OFF_BHI + k * 256 + phys * 16;
        cpasync16(d, whi + go);
        cpasync16(d + (OFF_BLO - OFF_BHI), wlo + go);
    }
}

__global__ void __launch_bounds__(256, 2)
gemm_tc(const float* __restrict__ x,
        const float* __restrict__ bspec, const float* __restrict__ bsh)
{
    extern __shared__ char smem[];
    const uint32_t sm32 = smem_u32(smem);
    const int tid  = threadIdx.x;
    const int wid  = tid >> 5;
    const int lane = tid & 31;
    const int wm0  = (wid & 3) * 32;
    const int wn0  = (wid >> 2) * 64;

    const int n0 = blockIdx.x * 128;
    const int m0 = blockIdx.y * 128;
    const int z  = blockIdx.z;

    const int zsel = (z < 8) ? (z >> 1) : 4;
    const float* xz = x + (size_t)zsel * BATCH * DIN;
    const __nv_bfloat16* whi = g_whi + (size_t)z * DIN * HDIM;
    const __nv_bfloat16* wlo = g_wlo + (size_t)z * DIN * HDIM;
    const float* bias = (z < 8) ? (bspec + z * HDIM) : (bsh + (z - 8) * HDIM);
    __half* outp = (z < 8) ? (g_spec + (size_t)z * BATCH * HDIM)
                           : (g_shared + (size_t)(z - 8) * BATCH * HDIM);

    float acc[2][8][4];
#pragma unroll
    for (int f = 0; f < 2; ++f)
#pragma unroll
        for (int j = 0; j < 8; ++j)
#pragma unroll
            for (int q = 0; q < 4; ++q) acc[f][j][q] = 0.f;

#pragma unroll
    for (int p = 0; p < 2; ++p) {
        issue_chunk(sm32, p, p * 32, xz, whi, wlo, m0, n0, tid);
        CP_COMMIT();
    }

    for (int kt = 0; kt < 16; ++kt) {
        CP_WAIT1();
        __syncthreads();

        if (kt + 2 < 16)
            issue_chunk(sm32, (kt + 2) % 3, (kt + 2) * 32, xz, whi, wlo, m0, n0, tid);
        CP_COMMIT();

        const uint32_t sa = sm32 + (kt % 3) * STG;
        const char* sp = smem + (kt % 3) * STG;
#pragma unroll
        for (int ksb = 0; ksb < 2; ++ksb) {
            const int kb = ksb * 16;
            uint32_t ah[2][4], al[2][4];
#pragma unroll
            for (int f = 0; f < 2; ++f) {
                const char* ap = sp + OFF_A
                    + (wm0 + f * 16 + (lane >> 2)) * A_STRIDE
                    + (kb + ((lane & 3) << 1)) * 4;
                const float2 v0 = *(const float2*)(ap);
                const float2 v1 = *(const float2*)(ap + 8 * A_STRIDE);
                const float2 v2 = *(const float2*)(ap + 32);
                const float2 v3 = *(const float2*)(ap + 8 * A_STRIDE + 32);
                split2(v0.x, v0.y, ah[f][0], al[f][0]);
                split2(v1.x, v1.y, ah[f][1], al[f][1]);
                split2(v2.x, v2.y, ah[f][2], al[f][2]);
                split2(v3.x, v3.y, ah[f][3], al[f][3]);
            }
            const int g = lane >> 3, r = lane & 7;
            const int krow = kb + (g & 1) * 8 + r;
#pragma unroll
            for (int c = 0; c < 4; ++c) {
                const int noff = wn0 + c * 16 + (g >> 1) * 8;
                const uint32_t u = (uint32_t)(noff >> 3);
                const uint32_t phys = (u & 8) | ((u & 7) ^ (uint32_t)(krow & 7));
                const uint32_t baddr = sa + OFF_BHI + krow * 256 + phys * 16;
                uint32_t bh[4], bl[4];
                ldsm4t(bh[0], bh[1], bh[2], bh[3], baddr);
                ldsm4t(bl[0], bl[1], bl[2], bl[3], baddr + (OFF_BLO - OFF_BHI));
#pragma unroll
                for (int f = 0; f < 2; ++f) {
#pragma unroll
                    for (int jj = 0; jj < 2; ++jj) {
                        float* d = acc[f][2 * c + jj];
                        mma16816(d, ah[f], bh[2 * jj], bh[2 * jj + 1]);
                        mma16816(d, ah[f], bl[2 * jj], bl[2 * jj + 1]);
                        mma16816(d, al[f], bh[2 * jj], bh[2 * jj + 1]);
                    }
                }
            }
        }
    }

    // epilogue: bias + relu -> fp16 stores (halved scratch traffic)
#pragma unroll
    for (int f = 0; f < 2; ++f) {
#pragma unroll
        for (int j = 0; j < 8; ++j) {
            const int row = m0 + wm0 + f * 16 + (lane >> 2);
            const int col = n0 + wn0 + j * 8 + (lane & 3) * 2;
            const float b0 = __ldg(&bias[col]);
            const float b1 = __ldg(&bias[col + 1]);
            const __half2 h0 = __floats2half2_rn(fmaxf(acc[f][j][0] + b0, 0.f),
                                                 fmaxf(acc[f][j][1] + b1, 0.f));
            const __half2 h1 = __floats2half2_rn(fmaxf(acc[f][j][2] + b0, 0.f),
                                                 fmaxf(acc[f][j][3] + b1, 0.f));
            *(__half2*)(outp + (size_t)row * HDIM + col)       = h0;
            *(__half2*)(outp + (size_t)(row + 8) * HDIM + col) = h1;
        }
    }
}

// ============================================================================
// Combine: 4 rows per block, 4 cols per thread, fp16 scratch loads, f32 math.
// ============================================================================
__global__ __launch_bounds__(256)
void combine_kernel(float* __restrict__ out)
{
    __shared__ float w[4][36];
    const int b0  = blockIdx.x * 4;
    const int tid = threadIdx.x;
    if (tid < 144) {
        const int row = tid / 36, e = tid % 36;
        float v;
        if (e < 24) v = g_gw[((size_t)(e / 6) * BATCH + b0 + row) * 6 + (e % 6)];
        else        v = g_gsw[(size_t)(b0 + row) * 12 + (e - 24)];
        w[row][e] = v;
    }
    __syncthreads();

    const int r = tid >> 6;
    const int b = b0 + r;
    const int h = (tid & 63) * 4;

    float4 sp[8];
#pragma unroll
    for (int j = 0; j < 8; ++j)
        sp[j] = ld_half4(g_spec + ((size_t)j * BATCH + b) * HDIM + h);
    float4 sh[4];
#pragma unroll
    for (int e = 0; e < 4; ++e)
        sh[e] = ld_half4(g_shared + ((size_t)e * BATCH + b) * HDIM + h);

    {
        float4 o = make_float4(0.f, 0.f, 0.f, 0.f);
#pragma unroll
        for (int j = 0; j < 8; ++j) {
            const float ww = w[r][24 + j];
            o.x = fmaf(ww, sp[j].x, o.x); o.y = fmaf(ww, sp[j].y, o.y);
            o.z = fmaf(ww, sp[j].z, o.z); o.w = fmaf(ww, sp[j].w, o.w);
        }
#pragma unroll
        for (int e = 0; e < 4; ++e) {
            const float ww = w[r][32 + e];
            o.x = fmaf(ww, sh[e].x, o.x); o.y = fmaf(ww, sh[e].y, o.y);
            o.z = fmaf(ww, sh[e].z, o.z); o.w = fmaf(ww, sh[e].w, o.w);
        }
        *(float4*)&out[((size_t)4 * BATCH + b) * HDIM + h] = o;
    }

#pragma unroll
    for (int n = 0; n < 4; ++n) {
        float4 o = make_float4(0.f, 0.f, 0.f, 0.f);
        const float w0 = w[r][n * 6 + 0], w1 = w[r][n * 6 + 1];
        o.x = w0 * sp[2 * n].x + w1 * sp[2 * n + 1].x;
        o.y = w0 * sp[2 * n].y + w1 * sp[2 * n + 1].y;
        o.z = w0 * sp[2 * n].z + w1 * sp[2 * n + 1].z;
        o.w = w0 * sp[2 * n].w + w1 * sp[2 * n + 1].w;
#pragma unroll
        for (int e = 0; e < 4; ++e) {
            const float ww = w[r][n * 6 + 2 + e];
            o.x = fmaf(ww, sh[e].x, o.x); o.y = fmaf(ww, sh[e].y, o.y);
            o.z = fmaf(ww, sh[e].z, o.z); o.w = fmaf(ww, sh[e].w, o.w);
        }
        *(float4*)&out[((size_t)n * BATCH + b) * HDIM + h] = o;
    }
}

// ============================================================================
extern "C" void kernel_launch(void* const* d_in, const int* in_sizes, int n_in,
                              void* d_out, int out_size)
{
    const float* x     = (const float*)d_in[0];
    const int*   sim   = (const int*)d_in[1];
    const float* Wspec = (const float*)d_in[2];
    const float* bspec = (const float*)d_in[3];
    const float* Wsh   = (const float*)d_in[4];
    const float* bsh   = (const float*)d_in[5];
    const float* Wg    = (const float*)d_in[6];
    const float* bg    = (const float*)d_in[7];
    const float* Wgs   = (const float*)d_in[8];
    const float* bgs   = (const float*)d_in[9];
    float* out = (float*)d_out;

    prep_kernel<<<WBLOCKS + TBLOCKS, 256>>>(
        (const float4*)Wspec, (const float4*)Wsh, Wg, Wgs);

    gates_kernel<<<BATCH / 8, 256>>>(x, bg, bgs, sim);

    cudaFuncSetAttribute(gemm_tc, cudaFuncAttributeMaxDynamicSharedMemorySize, GEMM_SMEM);
    dim3 gemm_grid(2, 128, 12);
    gemm_tc<<<gemm_grid, 256, GEMM_SMEM>>>(x, bspec, bsh);

    combine_kernel<<<BATCH / 4, 256>>>(out);
}

// round 17
// speedup vs baseline: 1.8081x; 1.3034x over previous
#include <cuda_runtime.h>
#include <cuda_fp16.h>
#include <math.h>
#include <stdint.h>

#define BATCH 16384
#define DIN   512
#define HDIM  256

// -------- scratch (static device allocations; no cudaMalloc allowed) --------
__device__ __half g_spec[8 * BATCH * HDIM];           // [z][b][h] fp16 scratch
__device__ __half g_shared[4 * BATCH * HDIM];         // [e][b][h] fp16 scratch
__device__ float g_gw[4 * BATCH * 6];                 // FINAL domain gate weights
__device__ float g_gsw[BATCH * 12];                   // FINAL shared gate weights
__device__ float g_wgt[36 * DIN];                     // TRANSPOSED gate weights [e][k]
__device__ __half g_whi[12 * DIN * HDIM];             // [z][k][n] fp16 hi
__device__ __half g_wlo[12 * DIN * HDIM];             // [z][k][n] fp16 lo residual

// ============================================================================
// helpers
// ============================================================================
__device__ __forceinline__ uint32_t smem_u32(const void* p) {
    uint32_t a;
    asm("{ .reg .u64 t; cvta.to.shared.u64 t, %1; cvt.u32.u64 %0, t; }" : "=r"(a) : "l"(p));
    return a;
}
__device__ __forceinline__ void cpasync16(uint32_t dst, const void* src) {
    asm volatile("cp.async.cg.shared.global [%0], [%1], 16;" :: "r"(dst), "l"(src) : "memory");
}
#define CP_COMMIT() asm volatile("cp.async.commit_group;" ::: "memory")
#define CP_WAIT1()  asm volatile("cp.async.wait_group 1;" ::: "memory")

__device__ __forceinline__ void ldsm4t(uint32_t& r0, uint32_t& r1, uint32_t& r2, uint32_t& r3, uint32_t addr) {
    asm volatile("ldmatrix.sync.aligned.m8n8.x4.trans.shared.b16 {%0,%1,%2,%3}, [%4];"
                 : "=r"(r0), "=r"(r1), "=r"(r2), "=r"(r3) : "r"(addr));
}
// fp16 x fp16 -> f32 accumulate
__device__ __forceinline__ void mma16816h(float* d, const uint32_t* a, uint32_t b0, uint32_t b1) {
    asm volatile(
        "mma.sync.aligned.m16n8k16.row.col.f32.f16.f16.f32 "
        "{%0,%1,%2,%3}, {%4,%5,%6,%7}, {%8,%9}, {%0,%1,%2,%3};"
        : "+f"(d[0]), "+f"(d[1]), "+f"(d[2]), "+f"(d[3])
        : "r"(a[0]), "r"(a[1]), "r"(a[2]), "r"(a[3]), "r"(b0), "r"(b1));
}

// pack two f32 -> fp16x2 (round-to-nearest)
__device__ __forceinline__ uint32_t cvt_f16x2(float a0, float a1) {
    uint32_t h;
    asm("cvt.rn.f16x2.f32 %0, %1, %2;" : "=r"(h) : "f"(a1), "f"(a0));
    return h;
}
// fp16 hi/lo split of two f32
__device__ __forceinline__ void split2h(float a0, float a1, uint32_t& hi, uint32_t& lo) {
    const uint32_t h = cvt_f16x2(a0, a1);
    const float2 hf = __half22float2(*(const __half2*)&h);
    lo = cvt_f16x2(a0 - hf.x, a1 - hf.y);
    hi = h;
}
// load 4 consecutive fp16 -> float4
__device__ __forceinline__ float4 ld_half4(const __half* p) {
    const uint2 u = *(const uint2*)p;
    const float2 fa = __half22float2(*(const __half2*)&u.x);
    const float2 fb = __half22float2(*(const __half2*)&u.y);
    return make_float4(fa.x, fa.y, fb.x, fb.y);
}

// ============================================================================
// Prep kernel: weight split f32->fp16 hi/lo + gate-weight transpose.
// ============================================================================
#define NWS4 (8 * DIN * HDIM / 4)           // 262144 float4
#define NWH4 (4 * DIN * HDIM / 4)           // 131072
#define WSBLK   (NWS4 / 1024)               // 256
#define WHBLK   (NWH4 / 1024)               // 128
#define WBLOCKS (WSBLK + WHBLK)             // 384
#define TBLOCKS 72                          // 18432 gate-weight elements / 256

__global__ __launch_bounds__(256)
void prep_kernel(const float4* __restrict__ Ws, const float4* __restrict__ Wh,
                 const float* __restrict__ Wg, const float* __restrict__ Wgs)
{
    if (blockIdx.x < WBLOCKS) {
        const float4* src;
        size_t dst0;
        if (blockIdx.x < WSBLK) {
            src  = Ws + (size_t)blockIdx.x * 1024;
            dst0 = (size_t)blockIdx.x * 1024;
        } else {
            src  = Wh + (size_t)(blockIdx.x - WSBLK) * 1024;
            dst0 = (size_t)NWS4 + (size_t)(blockIdx.x - WSBLK) * 1024;
        }
        const int t = threadIdx.x;
        float4 v0 = src[t];
        float4 v1 = src[t + 256];
        float4 v2 = src[t + 512];
        float4 v3 = src[t + 768];
        uint2* dh = (uint2*)g_whi;
        uint2* dl = (uint2*)g_wlo;
        uint32_t ha, la, hb, lb;
        split2h(v0.x, v0.y, ha, la); split2h(v0.z, v0.w, hb, lb);
        dh[dst0 + t]       = make_uint2(ha, hb); dl[dst0 + t]       = make_uint2(la, lb);
        split2h(v1.x, v1.y, ha, la); split2h(v1.z, v1.w, hb, lb);
        dh[dst0 + t + 256] = make_uint2(ha, hb); dl[dst0 + t + 256] = make_uint2(la, lb);
        split2h(v2.x, v2.y, ha, la); split2h(v2.z, v2.w, hb, lb);
        dh[dst0 + t + 512] = make_uint2(ha, hb); dl[dst0 + t + 512] = make_uint2(la, lb);
        split2h(v3.x, v3.y, ha, la); split2h(v3.z, v3.w, hb, lb);
        dh[dst0 + t + 768] = make_uint2(ha, hb); dl[dst0 + t + 768] = make_uint2(la, lb);
        return;
    }

    // gate-weight transpose: read coalesced, scatter to [e][k] rows
    const int idx = (blockIdx.x - WBLOCKS) * 256 + threadIdx.x;
    const int NDOM = 4 * DIN * 6;   // 12288
    if (idx < NDOM) {
        const int n = idx / (DIN * 6);
        const int rem = idx - n * DIN * 6;
        const int k = rem / 6;
        const int e = rem - k * 6;
        g_wgt[(n * 6 + e) * DIN + k] = Wg[idx];
    } else {
        const int j = idx - NDOM;   // < 6144
        const int k = j / 12;
        const int e = j - k * 12;
        g_wgt[(24 + e) * DIN + k] = Wgs[j];
    }
}

// ============================================================================
// Gates (R13-proven): warp per row, transposed weights from g_wgt.
// ============================================================================
__global__ __launch_bounds__(256)
void gates_kernel(const float* __restrict__ x,
                  const float* __restrict__ bg, const float* __restrict__ bgs,
                  const int* __restrict__ sim)
{
    const int b    = blockIdx.x * 8 + (threadIdx.x >> 5);
    const int lane = threadIdx.x & 31;

#pragma unroll
    for (int n = 0; n < 4; ++n) {
        const float* xr = x + ((size_t)n * BATCH + b) * DIN;
        float xv[16];
#pragma unroll
        for (int i = 0; i < 16; ++i) xv[i] = xr[lane + 32 * i];
        float zz[6];
#pragma unroll
        for (int e = 0; e < 6; ++e) {
            const float* wrow = g_wgt + (n * 6 + e) * DIN;
            float acc = 0.f;
#pragma unroll
            for (int i = 0; i < 16; ++i)
                acc = fmaf(xv[i], wrow[lane + 32 * i], acc);
#pragma unroll
            for (int o = 16; o; o >>= 1) acc += __shfl_xor_sync(0xffffffffu, acc, o);
            zz[e] = acc + bg[n * 6 + e];
        }
        float m1 = zz[0];
#pragma unroll
        for (int e = 1; e < 6; ++e) m1 = fmaxf(m1, zz[e]);
        float s1 = 0.f;
#pragma unroll
        for (int e = 0; e < 6; ++e) { zz[e] = __expf(zz[e] - m1); s1 += zz[e]; }
        const float inv1 = 1.f / s1;
#pragma unroll
        for (int e = 0; e < 6; ++e) zz[e] *= inv1;

        const int s0 = sim[n * 2], s1i = sim[n * 2 + 1];
        bool valid[6];
        valid[0] = true; valid[1] = true;
#pragma unroll
        for (int e = 0; e < 4; ++e) valid[2 + e] = (s0 == e) || (s1i == e);
        float m2 = -1e30f;
#pragma unroll
        for (int e = 0; e < 6; ++e) if (valid[e]) m2 = fmaxf(m2, zz[e]);
        float w[6]; float s2 = 0.f;
#pragma unroll
        for (int e = 0; e < 6; ++e) { w[e] = valid[e] ? __expf(zz[e] - m2) : 0.f; s2 += w[e]; }
        const float inv2 = 1.f / s2;
        if (lane == 0) {
#pragma unroll
            for (int e = 0; e < 6; ++e)
                g_gw[((size_t)n * BATCH + b) * 6 + e] = w[e] * inv2;
        }
    }
    {
        const float* xr = x + ((size_t)4 * BATCH + b) * DIN;
        float xv[16];
#pragma unroll
        for (int i = 0; i < 16; ++i) xv[i] = xr[lane + 32 * i];
        float gs[12];
#pragma unroll
        for (int e = 0; e < 12; ++e) {
            const float* wrow = g_wgt + (24 + e) * DIN;
            float acc = 0.f;
#pragma unroll
            for (int i = 0; i < 16; ++i)
                acc = fmaf(xv[i], wrow[lane + 32 * i], acc);
#pragma unroll
            for (int o = 16; o; o >>= 1) acc += __shfl_xor_sync(0xffffffffu, acc, o);
            gs[e] = acc + bgs[e];
        }
        float m = gs[0];
#pragma unroll
        for (int e = 1; e < 12; ++e) m = fmaxf(m, gs[e]);
        float s = 0.f;
#pragma unroll
        for (int e = 0; e < 12; ++e) { gs[e] = __expf(gs[e] - m); s += gs[e]; }
        const float inv = 1.f / s;
        if (lane == 0) {
#pragma unroll
            for (int e = 0; e < 12; ++e)
                g_gsw[(size_t)b * 12 + e] = gs[e] * inv;
        }
    }
}

// ============================================================================
// Tensor-core GEMM: fp16 MMA, asymmetric split — A single fp16 (converted in
// registers from raw f32), B pre-split fp16 hi/lo. 2 MMAs per fragment pair
// (was 3 with bf16). CTA tile 128x128, BK=32, 3-stage cp.async, 2 CTA/SM.
// ============================================================================
#define OFF_A   0
#define A_STRIDE 160
#define OFF_BHI 20480
#define OFF_BLO 28672
#define STG     36864
#define GEMM_SMEM (3 * STG)   // 110592

__device__ __forceinline__ void issue_chunk(
    uint32_t sm32, int stage, int c0,
    const float* __restrict__ xz,
    const __half* __restrict__ whi, const __half* __restrict__ wlo,
    int m0, int n0, int tid)
{
    const uint32_t sa = sm32 + stage * STG;
#pragma unroll
    for (int i = 0; i < 4; ++i) {
        const int idx = tid + i * 256;
        const int m = idx >> 3, u = idx & 7;
        const float* src = xz + (size_t)(m0 + m) * DIN + c0 + u * 4;
        cpasync16(sa + OFF_A + m * A_STRIDE + u * 16, src);
    }
#pragma unroll
    for (int i = 0; i < 2; ++i) {
        const int idx = tid + i * 256;
        const int k = idx >> 4, u = idx & 15;
        const size_t go = (size_t)(c0 + k) * HDIM + n0 + u * 8;
        const uint32_t phys = (u & 8) | ((u & 7) ^ (k & 7));
        const uint32_t d = sa + OFF_BHI + k * 256 + phys * 16;
        cpasync16(d, whi + go);
        cpasync16(d + (OFF_BLO - OFF_BHI), wlo + go);
    }
}

__global__ void __launch_bounds__(256, 2)
gemm_tc(const float* __restrict__ x,
        const float* __restrict__ bspec, const float* __restrict__ bsh)
{
    extern __shared__ char smem[];
    const uint32_t sm32 = smem_u32(smem);
    const int tid  = threadIdx.x;
    const int wid  = tid >> 5;
    const int lane = tid & 31;
    const int wm0  = (wid & 3) * 32;
    const int wn0  = (wid >> 2) * 64;

    const int n0 = blockIdx.x * 128;
    const int m0 = blockIdx.y * 128;
    const int z  = blockIdx.z;

    const int zsel = (z < 8) ? (z >> 1) : 4;
    const float* xz = x + (size_t)zsel * BATCH * DIN;
    const __half* whi = g_whi + (size_t)z * DIN * HDIM;
    const __half* wlo = g_wlo + (size_t)z * DIN * HDIM;
    const float* bias = (z < 8) ? (bspec + z * HDIM) : (bsh + (z - 8) * HDIM);
    __half* outp = (z < 8) ? (g_spec + (size_t)z * BATCH * HDIM)
                           : (g_shared + (size_t)(z - 8) * BATCH * HDIM);

    float acc[2][8][4];
#pragma unroll
    for (int f = 0; f < 2; ++f)
#pragma unroll
        for (int j = 0; j < 8; ++j)
#pragma unroll
            for (int q = 0; q < 4; ++q) acc[f][j][q] = 0.f;

#pragma unroll
    for (int p = 0; p < 2; ++p) {
        issue_chunk(sm32, p, p * 32, xz, whi, wlo, m0, n0, tid);
        CP_COMMIT();
    }

    for (int kt = 0; kt < 16; ++kt) {
        CP_WAIT1();
        __syncthreads();

        if (kt + 2 < 16)
            issue_chunk(sm32, (kt + 2) % 3, (kt + 2) * 32, xz, whi, wlo, m0, n0, tid);
        CP_COMMIT();

        const uint32_t sa = sm32 + (kt % 3) * STG;
        const char* sp = smem + (kt % 3) * STG;
#pragma unroll
        for (int ksb = 0; ksb < 2; ++ksb) {
            const int kb = ksb * 16;
            // ---- A fragments: lds.64 f32 pairs -> single packed fp16 cvt
            uint32_t ah[2][4];
#pragma unroll
            for (int f = 0; f < 2; ++f) {
                const char* ap = sp + OFF_A
                    + (wm0 + f * 16 + (lane >> 2)) * A_STRIDE
                    + (kb + ((lane & 3) << 1)) * 4;
                const float2 v0 = *(const float2*)(ap);
                const float2 v1 = *(const float2*)(ap + 8 * A_STRIDE);
                const float2 v2 = *(const float2*)(ap + 32);
                const float2 v3 = *(const float2*)(ap + 8 * A_STRIDE + 32);
                ah[f][0] = cvt_f16x2(v0.x, v0.y);
                ah[f][1] = cvt_f16x2(v1.x, v1.y);
                ah[f][2] = cvt_f16x2(v2.x, v2.y);
                ah[f][3] = cvt_f16x2(v3.x, v3.y);
            }
            const int g = lane >> 3, r = lane & 7;
            const int krow = kb + (g & 1) * 8 + r;
#pragma unroll
            for (int c = 0; c < 4; ++c) {
                const int noff = wn0 + c * 16 + (g >> 1) * 8;
                const uint32_t u = (uint32_t)(noff >> 3);
                const uint32_t phys = (u & 8) | ((u & 7) ^ (uint32_t)(krow & 7));
                const uint32_t baddr = sa + OFF_BHI + krow * 256 + phys * 16;
                uint32_t bh[4], bl[4];
                ldsm4t(bh[0], bh[1], bh[2], bh[3], baddr);
                ldsm4t(bl[0], bl[1], bl[2], bl[3], baddr + (OFF_BLO - OFF_BHI));
#pragma unroll
                for (int f = 0; f < 2; ++f) {
#pragma unroll
                    for (int jj = 0; jj < 2; ++jj) {
                        float* d = acc[f][2 * c + jj];
                        mma16816h(d, ah[f], bh[2 * jj], bh[2 * jj + 1]);
                        mma16816h(d, ah[f], bl[2 * jj], bl[2 * jj + 1]);
                    }
                }
            }
        }
    }

    // epilogue: bias + relu -> fp16 stores
#pragma unroll
    for (int f = 0; f < 2; ++f) {
#pragma unroll
        for (int j = 0; j < 8; ++j) {
            const int row = m0 + wm0 + f * 16 + (lane >> 2);
            const int col = n0 + wn0 + j * 8 + (lane & 3) * 2;
            const float b0 = __ldg(&bias[col]);
            const float b1 = __ldg(&bias[col + 1]);
            const __half2 h0 = __floats2half2_rn(fmaxf(acc[f][j][0] + b0, 0.f),
                                                 fmaxf(acc[f][j][1] + b1, 0.f));
            const __half2 h1 = __floats2half2_rn(fmaxf(acc[f][j][2] + b0, 0.f),
                                                 fmaxf(acc[f][j][3] + b1, 0.f));
            *(__half2*)(outp + (size_t)row * HDIM + col)       = h0;
            *(__half2*)(outp + (size_t)(row + 8) * HDIM + col) = h1;
        }
    }
}

// ============================================================================
// Combine: 4 rows per block, 4 cols per thread, fp16 scratch loads, f32 math.
// ============================================================================
__global__ __launch_bounds__(256)
void combine_kernel(float* __restrict__ out)
{
    __shared__ float w[4][36];
    const int b0  = blockIdx.x * 4;
    const int tid = threadIdx.x;
    if (tid < 144) {
        const int row = tid / 36, e = tid % 36;
        float v;
        if (e < 24) v = g_gw[((size_t)(e / 6) * BATCH + b0 + row) * 6 + (e % 6)];
        else        v = g_gsw[(size_t)(b0 + row) * 12 + (e - 24)];
        w[row][e] = v;
    }
    __syncthreads();

    const int r = tid >> 6;
    const int b = b0 + r;
    const int h = (tid & 63) * 4;

    float4 sp[8];
#pragma unroll
    for (int j = 0; j < 8; ++j)
        sp[j] = ld_half4(g_spec + ((size_t)j * BATCH + b) * HDIM + h);
    float4 sh[4];
#pragma unroll
    for (int e = 0; e < 4; ++e)
        sh[e] = ld_half4(g_shared + ((size_t)e * BATCH + b) * HDIM + h);

    {
        float4 o = make_float4(0.f, 0.f, 0.f, 0.f);
#pragma unroll
        for (int j = 0; j < 8; ++j) {
            const float ww = w[r][24 + j];
            o.x = fmaf(ww, sp[j].x, o.x); o.y = fmaf(ww, sp[j].y, o.y);
            o.z = fmaf(ww, sp[j].z, o.z); o.w = fmaf(ww, sp[j].w, o.w);
        }
#pragma unroll
        for (int e = 0; e < 4; ++e) {
            const float ww = w[r][32 + e];
            o.x = fmaf(ww, sh[e].x, o.x); o.y = fmaf(ww, sh[e].y, o.y);
            o.z = fmaf(ww, sh[e].z, o.z); o.w = fmaf(ww, sh[e].w, o.w);
        }
        *(float4*)&out[((size_t)4 * BATCH + b) * HDIM + h] = o;
    }

#pragma unroll
    for (int n = 0; n < 4; ++n) {
        float4 o = make_float4(0.f, 0.f, 0.f, 0.f);
        const float w0 = w[r][n * 6 + 0], w1 = w[r][n * 6 + 1];
        o.x = w0 * sp[2 * n].x + w1 * sp[2 * n + 1].x;
        o.y = w0 * sp[2 * n].y + w1 * sp[2 * n + 1].y;
        o.z = w0 * sp[2 * n].z + w1 * sp[2 * n + 1].z;
        o.w = w0 * sp[2 * n].w + w1 * sp[2 * n + 1].w;
#pragma unroll
        for (int e = 0; e < 4; ++e) {
            const float ww = w[r][n * 6 + 2 + e];
            o.x = fmaf(ww, sh[e].x, o.x); o.y = fmaf(ww, sh[e].y, o.y);
            o.z = fmaf(ww, sh[e].z, o.z); o.w = fmaf(ww, sh[e].w, o.w);
        }
        *(float4*)&out[((size_t)n * BATCH + b) * HDIM + h] = o;
    }
}

// ============================================================================
extern "C" void kernel_launch(void* const* d_in, const int* in_sizes, int n_in,
                              void* d_out, int out_size)
{
    const float* x     = (const float*)d_in[0];
    const int*   sim   = (const int*)d_in[1];
    const float* Wspec = (const float*)d_in[2];
    const float* bspec = (const float*)d_in[3];
    const float* Wsh   = (const float*)d_in[4];
    const float* bsh   = (const float*)d_in[5];
    const float* Wg    = (const float*)d_in[6];
    const float* bg    = (const float*)d_in[7];
    const float* Wgs   = (const float*)d_in[8];
    const float* bgs   = (const float*)d_in[9];
    float* out = (float*)d_out;

    prep_kernel<<<WBLOCKS + TBLOCKS, 256>>>(
        (const float4*)Wspec, (const float4*)Wsh, Wg, Wgs);

    gates_kernel<<<BATCH / 8, 256>>>(x, bg, bgs, sim);

    cudaFuncSetAttribute(gemm_tc, cudaFuncAttributeMaxDynamicSharedMemorySize, GEMM_SMEM);
    dim3 gemm_grid(2, 128, 12);
    gemm_tc<<<gemm_grid, 256, GEMM_SMEM>>>(x, bspec, bsh);

    combine_kernel<<<BATCH / 4, 256>>>(out);
}